// round 1
// baseline (speedup 1.0000x reference)
#include <cuda_runtime.h>
#include <math.h>

// Quaternion LSTM: T=128, B=64, F=512, H=1024.
// Round 0: correct fp32 baseline.
//   1. Expand Hamilton matrices Wcat (512 x 4096), Ucat (1024 x 4096) once per call.
//   2. One big GEMM for all input projections G = x @ Wcat + bias  (8192 x 4096).
//   3. 128 sequential steps: pre = h @ Ucat (split-K x4), then fused gate/update.
//   4. One big GEMM for all outputs: out = Hbuf @ fco_w + fco_b (8192 x 513).

#define T_ 128
#define B_ 64
#define Fdim 512
#define H_ 1024
#define N4 (4 * H_)        // 4096 (4 gates concatenated: f, i, o, c)
#define FO (Fdim + 1)      // 513
#define SPLITK 4
#define KCHUNK (H_ / SPLITK)  // 256

// ---- scratch (static device globals: allocation-free) ----
__device__ float g_Wcat[(size_t)Fdim * N4];            //  8 MB
__device__ float g_bias4[N4];
__device__ float g_Ucat[(size_t)H_ * N4];              // 16 MB
__device__ float g_G[(size_t)T_ * B_ * N4];            // 128 MB (pre-gates)
__device__ float g_preK[(size_t)SPLITK * B_ * N4];     //  4 MB
__device__ float g_h[2 * B_ * H_];                     // double-buffered hidden
__device__ float g_c[B_ * H_];
__device__ float g_Hbuf[(size_t)T_ * B_ * H_];         // 32 MB (all h_t)

// Hamilton layout: M[rb*In4+a, cb*Out4+b] = sgn[cb][rb] * w[rb^cb][a][b]
__device__ const float c_sgn[16] = {
    1.f, -1.f, -1.f, -1.f,   // cb=0 : [ r, -i, -j, -k]
    1.f,  1.f, -1.f,  1.f,   // cb=1 : [ i,  r, -k,  j]
    1.f,  1.f,  1.f, -1.f,   // cb=2 : [ j,  k,  r, -i]
    1.f, -1.f,  1.f,  1.f    // cb=3 : [ k, -j,  i,  r]
};

// ---------------- init ----------------
__global__ void init_state() {
    int idx = blockIdx.x * blockDim.x + threadIdx.x;
    if (idx < 2 * B_ * H_) g_h[idx] = 0.f;
    if (idx < B_ * H_)     g_c[idx] = 0.f;
}

// ---------------- build Hamilton matrices ----------------
__global__ void build_W(const float* __restrict__ wf, const float* __restrict__ wi,
                        const float* __restrict__ wo, const float* __restrict__ wc) {
    int idx = blockIdx.x * blockDim.x + threadIdx.x;
    if (idx >= Fdim * N4) return;
    int row  = idx / N4;          // 0..511   (input dim)
    int col  = idx % N4;          // 0..4095
    int gate = col / H_;
    int cj   = col % H_;
    int rb = row / (Fdim / 4), a = row % (Fdim / 4);
    int cb = cj / (H_ / 4),    b = cj % (H_ / 4);
    const float* w = (gate == 0) ? wf : (gate == 1) ? wi : (gate == 2) ? wo : wc;
    int comp = rb ^ cb;
    g_Wcat[idx] = c_sgn[cb * 4 + rb] *
                  w[((size_t)comp * (Fdim / 4) + a) * (H_ / 4) + b];
}

__global__ void build_U(const float* __restrict__ uf, const float* __restrict__ ui,
                        const float* __restrict__ uo, const float* __restrict__ uc) {
    int idx = blockIdx.x * blockDim.x + threadIdx.x;
    if (idx >= H_ * N4) return;
    int row  = idx / N4;          // 0..1023
    int col  = idx % N4;
    int gate = col / H_;
    int cj   = col % H_;
    int rb = row / (H_ / 4), a = row % (H_ / 4);
    int cb = cj / (H_ / 4),  b = cj % (H_ / 4);
    const float* w = (gate == 0) ? uf : (gate == 1) ? ui : (gate == 2) ? uo : uc;
    int comp = rb ^ cb;
    g_Ucat[idx] = c_sgn[cb * 4 + rb] *
                  w[((size_t)comp * (H_ / 4) + a) * (H_ / 4) + b];
}

__global__ void build_bias(const float* __restrict__ bf, const float* __restrict__ bi,
                           const float* __restrict__ bo, const float* __restrict__ bc) {
    int idx = blockIdx.x * blockDim.x + threadIdx.x;
    if (idx >= N4) return;
    int gate = idx / H_, j = idx % H_;
    const float* b = (gate == 0) ? bf : (gate == 1) ? bi : (gate == 2) ? bo : bc;
    g_bias4[idx] = b[j];
}

// ---------------- generic fp32 GEMM (128x128 tile, 8x8 microtile) ----------------
__device__ __forceinline__ void gemm_body(const float* __restrict__ A,
                                          const float* __restrict__ Bm,
                                          const float* __restrict__ bias,
                                          float* __restrict__ C,
                                          int M, int N, int K) {
    const int BM = 128, BN = 128, BK = 16;
    __shared__ float As[BK][BM];
    __shared__ float Bs[BK][BN];
    int tid = threadIdx.x;
    int tx = tid % 16, ty = tid / 16;   // 16x16 threads, 8x8 outputs each
    int rowBase = blockIdx.y * BM;
    int colBase = blockIdx.x * BN;
    float acc[8][8];
    #pragma unroll
    for (int i = 0; i < 8; i++)
        #pragma unroll
        for (int j = 0; j < 8; j++) acc[i][j] = 0.f;

    for (int k0 = 0; k0 < K; k0 += BK) {
        #pragma unroll
        for (int i = tid; i < BM * BK; i += 256) {
            int m = i / BK, kk = i % BK;
            int gm = rowBase + m, gk = k0 + kk;
            float v = 0.f;
            if (gm < M) v = A[(size_t)gm * K + gk];
            As[kk][m] = v;
        }
        #pragma unroll
        for (int i = tid; i < BK * BN; i += 256) {
            int kk = i / BN, n = i % BN;
            int gk = k0 + kk, gn = colBase + n;
            float v = 0.f;
            if (gn < N) v = Bm[(size_t)gk * N + gn];
            Bs[kk][n] = v;
        }
        __syncthreads();
        #pragma unroll
        for (int kk = 0; kk < BK; kk++) {
            float a[8], b[8];
            float4 a0 = *reinterpret_cast<const float4*>(&As[kk][ty * 8]);
            float4 a1 = *reinterpret_cast<const float4*>(&As[kk][ty * 8 + 4]);
            float4 b0 = *reinterpret_cast<const float4*>(&Bs[kk][tx * 8]);
            float4 b1 = *reinterpret_cast<const float4*>(&Bs[kk][tx * 8 + 4]);
            a[0]=a0.x; a[1]=a0.y; a[2]=a0.z; a[3]=a0.w;
            a[4]=a1.x; a[5]=a1.y; a[6]=a1.z; a[7]=a1.w;
            b[0]=b0.x; b[1]=b0.y; b[2]=b0.z; b[3]=b0.w;
            b[4]=b1.x; b[5]=b1.y; b[6]=b1.z; b[7]=b1.w;
            #pragma unroll
            for (int i = 0; i < 8; i++)
                #pragma unroll
                for (int j = 0; j < 8; j++)
                    acc[i][j] += a[i] * b[j];
        }
        __syncthreads();
    }
    #pragma unroll
    for (int i = 0; i < 8; i++) {
        int gm = rowBase + ty * 8 + i;
        if (gm >= M) continue;
        #pragma unroll
        for (int j = 0; j < 8; j++) {
            int gn = colBase + tx * 8 + j;
            if (gn >= N) continue;
            float v = acc[i][j];
            if (bias) v += bias[gn];
            C[(size_t)gm * N + gn] = v;
        }
    }
}

__global__ __launch_bounds__(256) void gemm_in(const float* __restrict__ x) {
    gemm_body(x, g_Wcat, g_bias4, g_G, T_ * B_, N4, Fdim);
}

__global__ __launch_bounds__(256) void gemm_out(const float* __restrict__ fw,
                                                const float* __restrict__ fb,
                                                float* __restrict__ out) {
    gemm_body(g_Hbuf, fw, fb, out, T_ * B_, FO, H_);
}

// ---------------- recurrent step: pre = h @ Ucat (split-K) ----------------
__global__ __launch_bounds__(256) void step_gemm(int t) {
    const float* __restrict__ h = g_h + (size_t)(t & 1) * (B_ * H_);
    int s = blockIdx.y;                 // K split
    int colBase = blockIdx.x * 64;      // 64 n-tiles
    int k0base = s * KCHUNK;
    int tid = threadIdx.x;
    int tx = tid % 16, ty = tid / 16;   // 16x16 threads, 4x4 outputs each
    __shared__ float As[16][64];
    __shared__ float Bs[16][64];
    float acc[4][4];
    #pragma unroll
    for (int i = 0; i < 4; i++)
        #pragma unroll
        for (int j = 0; j < 4; j++) acc[i][j] = 0.f;

    for (int k0 = 0; k0 < KCHUNK; k0 += 16) {
        #pragma unroll
        for (int i = tid; i < 64 * 16; i += 256) {
            int m = i / 16, kk = i % 16;
            As[kk][m] = h[(size_t)m * H_ + k0base + k0 + kk];
        }
        #pragma unroll
        for (int i = tid; i < 16 * 64; i += 256) {
            int kk = i / 64, n = i % 64;
            Bs[kk][n] = g_Ucat[(size_t)(k0base + k0 + kk) * N4 + colBase + n];
        }
        __syncthreads();
        #pragma unroll
        for (int kk = 0; kk < 16; kk++) {
            float4 av = *reinterpret_cast<const float4*>(&As[kk][ty * 4]);
            float4 bv = *reinterpret_cast<const float4*>(&Bs[kk][tx * 4]);
            float a[4] = {av.x, av.y, av.z, av.w};
            float b[4] = {bv.x, bv.y, bv.z, bv.w};
            #pragma unroll
            for (int i = 0; i < 4; i++)
                #pragma unroll
                for (int j = 0; j < 4; j++)
                    acc[i][j] += a[i] * b[j];
        }
        __syncthreads();
    }
    float* out = g_preK + (size_t)s * B_ * N4;
    #pragma unroll
    for (int i = 0; i < 4; i++) {
        int m = ty * 4 + i;
        #pragma unroll
        for (int j = 0; j < 4; j++)
            out[(size_t)m * N4 + colBase + tx * 4 + j] = acc[i][j];
    }
}

// ---------------- recurrent step: gates + state update ----------------
__global__ __launch_bounds__(256) void step_update(int t) {
    int idx = blockIdx.x * blockDim.x + threadIdx.x;
    if (idx >= B_ * H_) return;
    int b = idx / H_;
    int j = idx % H_;
    const float* Gt = g_G + (size_t)((size_t)t * B_ + b) * N4;
    float pf = Gt[0 * H_ + j];
    float pi = Gt[1 * H_ + j];
    float po = Gt[2 * H_ + j];
    float pa = Gt[3 * H_ + j];
    #pragma unroll
    for (int s = 0; s < SPLITK; s++) {
        const float* pk = g_preK + (size_t)s * B_ * N4 + (size_t)b * N4;
        pf += pk[0 * H_ + j];
        pi += pk[1 * H_ + j];
        po += pk[2 * H_ + j];
        pa += pk[3 * H_ + j];
    }
    float f = 1.f / (1.f + expf(-pf));
    float i = 1.f / (1.f + expf(-pi));
    float o = 1.f / (1.f + expf(-po));
    float cprev = g_c[idx];
    float cnew = i * tanhf(pa) + f * cprev;
    float hnew = o * tanhf(cnew);
    g_c[idx] = cnew;
    g_h[(size_t)((t + 1) & 1) * (B_ * H_) + idx] = hnew;
    g_Hbuf[(size_t)t * B_ * H_ + idx] = hnew;
}

// ---------------- launch ----------------
extern "C" void kernel_launch(void* const* d_in, const int* in_sizes, int n_in,
                              void* d_out, int out_size) {
    const float* x    = (const float*)d_in[0];
    const float* wfxw = (const float*)d_in[1];
    const float* wfxb = (const float*)d_in[2];
    const float* wixw = (const float*)d_in[3];
    const float* wixb = (const float*)d_in[4];
    const float* woxw = (const float*)d_in[5];
    const float* woxb = (const float*)d_in[6];
    const float* wcxw = (const float*)d_in[7];
    const float* wcxb = (const float*)d_in[8];
    const float* ufhw = (const float*)d_in[9];
    const float* uihw = (const float*)d_in[10];
    const float* uohw = (const float*)d_in[11];
    const float* uchw = (const float*)d_in[12];
    const float* fcow = (const float*)d_in[13];
    const float* fcob = (const float*)d_in[14];
    float* out = (float*)d_out;

    init_state<<<(2 * B_ * H_ + 255) / 256, 256>>>();
    build_W<<<(Fdim * N4 + 255) / 256, 256>>>(wfxw, wixw, woxw, wcxw);
    build_bias<<<(N4 + 255) / 256, 256>>>(wfxb, wixb, woxb, wcxb);
    build_U<<<(H_ * N4 + 255) / 256, 256>>>(ufhw, uihw, uohw, uchw);

    {   // input projections for the whole sequence
        dim3 grid(N4 / 128, (T_ * B_) / 128);
        gemm_in<<<grid, 256>>>(x);
    }

    for (int t = 0; t < T_; t++) {
        dim3 grid(N4 / 64, SPLITK);       // 64 x 4 = 256 CTAs
        step_gemm<<<grid, 256>>>(t);
        step_update<<<(B_ * H_ + 255) / 256, 256>>>(t);
    }

    {   // output projection for all timesteps at once
        dim3 grid((FO + 127) / 128, (T_ * B_) / 128);
        gemm_out<<<grid, 256>>>(fcow, fcob, out);
    }
}

// round 6
// speedup vs baseline: 1.2294x; 1.2294x over previous
#include <cuda_runtime.h>
#include <math.h>

// Quaternion LSTM: T=128, B=64, F=512, H=1024.
// Round 6: pure fp32 C++ (the only path that runs on this harness/target).
//   Round-0 structure (passed @6311us) + tuned recurrence:
//   - step GEMM: 64x128 tile, split-K x8 (256 CTAs), 4x8 microtile, BK=16
//   - vectorized (float4) gate/state update
//   - big GEMMs unchanged (128x128, 8x8 micro)

#define T_ 128
#define B_ 64
#define Fdim 512
#define H_ 1024
#define N4 (4 * H_)          // 4096
#define FO (Fdim + 1)        // 513
#define SPLITK 8
#define KCHUNK (H_ / SPLITK) // 128

// ---- scratch (static device globals: allocation-free) ----
__device__ float g_Wcat[(size_t)Fdim * N4];            //  8 MB
__device__ float g_bias4[N4];
__device__ float g_Ucat[(size_t)H_ * N4];              // 16 MB
__device__ float g_G[(size_t)T_ * B_ * N4];            // 128 MB (pre-gates)
__device__ float g_preK[(size_t)SPLITK * B_ * N4];     //  8 MB
__device__ float g_h[2 * B_ * H_];                     // double-buffered hidden
__device__ float g_c[B_ * H_];
__device__ float g_Hbuf[(size_t)T_ * B_ * H_];         // 32 MB

__device__ const float c_sgn[16] = {
    1.f, -1.f, -1.f, -1.f,
    1.f,  1.f, -1.f,  1.f,
    1.f,  1.f,  1.f, -1.f,
    1.f, -1.f,  1.f,  1.f
};

// ---------------- init ----------------
__global__ void init_state() {
    int idx = blockIdx.x * blockDim.x + threadIdx.x;
    if (idx < 2 * B_ * H_) g_h[idx] = 0.f;
    if (idx < B_ * H_)     g_c[idx] = 0.f;
}

// ---------------- build Hamilton matrices ----------------
__global__ void build_W(const float* __restrict__ wf, const float* __restrict__ wi,
                        const float* __restrict__ wo, const float* __restrict__ wc) {
    int idx = blockIdx.x * blockDim.x + threadIdx.x;
    if (idx >= Fdim * N4) return;
    int row  = idx / N4;
    int col  = idx % N4;
    int gate = col / H_;
    int cj   = col % H_;
    int rb = row / (Fdim / 4), a = row % (Fdim / 4);
    int cb = cj / (H_ / 4),    b = cj % (H_ / 4);
    const float* w = (gate == 0) ? wf : (gate == 1) ? wi : (gate == 2) ? wo : wc;
    g_Wcat[idx] = c_sgn[cb * 4 + rb] *
                  w[((size_t)(rb ^ cb) * (Fdim / 4) + a) * (H_ / 4) + b];
}

__global__ void build_U(const float* __restrict__ uf, const float* __restrict__ ui,
                        const float* __restrict__ uo, const float* __restrict__ uc) {
    int idx = blockIdx.x * blockDim.x + threadIdx.x;
    if (idx >= H_ * N4) return;
    int row  = idx / N4;
    int col  = idx % N4;
    int gate = col / H_;
    int cj   = col % H_;
    int rb = row / (H_ / 4), a = row % (H_ / 4);
    int cb = cj / (H_ / 4),  b = cj % (H_ / 4);
    const float* w = (gate == 0) ? uf : (gate == 1) ? ui : (gate == 2) ? uo : uc;
    g_Ucat[idx] = c_sgn[cb * 4 + rb] *
                  w[((size_t)(rb ^ cb) * (H_ / 4) + a) * (H_ / 4) + b];
}

__global__ void build_bias(const float* __restrict__ bf, const float* __restrict__ bi,
                           const float* __restrict__ bo, const float* __restrict__ bc) {
    int idx = blockIdx.x * blockDim.x + threadIdx.x;
    if (idx >= N4) return;
    int gate = idx / H_, j = idx % H_;
    const float* b = (gate == 0) ? bf : (gate == 1) ? bi : (gate == 2) ? bo : bc;
    g_bias4[idx] = b[j];
}

// ---------------- generic fp32 GEMM (128x128 tile, 8x8 microtile) ----------------
__device__ __forceinline__ void gemm_body(const float* __restrict__ A,
                                          const float* __restrict__ Bm,
                                          const float* __restrict__ bias,
                                          float* __restrict__ C,
                                          int M, int N, int K) {
    const int BM = 128, BN = 128, BK = 16;
    __shared__ float As[BK][BM];
    __shared__ float Bs[BK][BN];
    int tid = threadIdx.x;
    int tx = tid % 16, ty = tid / 16;   // 16x16 threads, 8x8 outputs each
    int rowBase = blockIdx.y * BM;
    int colBase = blockIdx.x * BN;
    float acc[8][8];
    #pragma unroll
    for (int i = 0; i < 8; i++)
        #pragma unroll
        for (int j = 0; j < 8; j++) acc[i][j] = 0.f;

    for (int k0 = 0; k0 < K; k0 += BK) {
        // A: 128x16 as 512 float4 / 256 threads (coalesced, transposed store)
        #pragma unroll
        for (int i = 0; i < 2; i++) {
            int lin = tid + i * 256;
            int r = lin >> 2, c4 = (lin & 3) * 4;
            float4 v = *reinterpret_cast<const float4*>(
                &A[(size_t)(rowBase + r) * K + k0 + c4]);
            As[c4 + 0][r] = v.x;
            As[c4 + 1][r] = v.y;
            As[c4 + 2][r] = v.z;
            As[c4 + 3][r] = v.w;
        }
        // B: 16x128 (scalar, N-guarded)
        #pragma unroll
        for (int i = 0; i < 8; i++) {
            int lin = tid + i * 256;
            int kk = lin >> 7, n = lin & 127;
            int gn = colBase + n;
            float v = 0.f;
            if (gn < N) v = Bm[(size_t)(k0 + kk) * N + gn];
            Bs[kk][n] = v;
        }
        __syncthreads();
        #pragma unroll
        for (int kk = 0; kk < BK; kk++) {
            float a[8], b[8];
            float4 a0 = *reinterpret_cast<const float4*>(&As[kk][ty * 8]);
            float4 a1 = *reinterpret_cast<const float4*>(&As[kk][ty * 8 + 4]);
            float4 b0 = *reinterpret_cast<const float4*>(&Bs[kk][tx * 8]);
            float4 b1 = *reinterpret_cast<const float4*>(&Bs[kk][tx * 8 + 4]);
            a[0]=a0.x; a[1]=a0.y; a[2]=a0.z; a[3]=a0.w;
            a[4]=a1.x; a[5]=a1.y; a[6]=a1.z; a[7]=a1.w;
            b[0]=b0.x; b[1]=b0.y; b[2]=b0.z; b[3]=b0.w;
            b[4]=b1.x; b[5]=b1.y; b[6]=b1.z; b[7]=b1.w;
            #pragma unroll
            for (int i = 0; i < 8; i++)
                #pragma unroll
                for (int j = 0; j < 8; j++)
                    acc[i][j] += a[i] * b[j];
        }
        __syncthreads();
    }
    #pragma unroll
    for (int i = 0; i < 8; i++) {
        int gm = rowBase + ty * 8 + i;
        if (gm >= M) continue;
        #pragma unroll
        for (int j = 0; j < 8; j++) {
            int gn = colBase + tx * 8 + j;
            if (gn >= N) continue;
            float v = acc[i][j];
            if (bias) v += bias[gn];
            C[(size_t)gm * N + gn] = v;
        }
    }
}

__global__ __launch_bounds__(256) void gemm_in(const float* __restrict__ x) {
    gemm_body(x, g_Wcat, g_bias4, g_G, T_ * B_, N4, Fdim);
}

__global__ __launch_bounds__(256) void gemm_out(const float* __restrict__ fw,
                                                const float* __restrict__ fb,
                                                float* __restrict__ out) {
    gemm_body(g_Hbuf, fw, fb, out, T_ * B_, FO, H_);
}

// ---------------- recurrent step: pre = h @ Ucat (split-K x8) ----------------
// 64x128 tile, BK=16, 256 threads (16x16), thread = 4 rows x 8 cols.
__global__ __launch_bounds__(256) void step_gemm(int t) {
    const float* __restrict__ h = g_h + (size_t)(t & 1) * (B_ * H_);
    __shared__ float As[16][68];    // [kk][m] (pad 68)
    __shared__ float Bs[16][132];   // [kk][n] (pad 132)
    int tid = threadIdx.x;
    int tx = tid & 15, ty = tid >> 4;
    int colBase = blockIdx.x * 128;
    int s = blockIdx.y;
    int kbase = s * KCHUNK;

    float acc[4][8];
    #pragma unroll
    for (int i = 0; i < 4; i++)
        #pragma unroll
        for (int j = 0; j < 8; j++) acc[i][j] = 0.f;

    for (int k0 = 0; k0 < KCHUNK; k0 += 16) {
        {   // A: 64x16 = 256 float4, one per thread (transposed store)
            int r = tid >> 2, c4 = (tid & 3) * 4;
            float4 v = *reinterpret_cast<const float4*>(
                &h[(size_t)r * H_ + kbase + k0 + c4]);
            As[c4 + 0][r] = v.x;
            As[c4 + 1][r] = v.y;
            As[c4 + 2][r] = v.z;
            As[c4 + 3][r] = v.w;
        }
        #pragma unroll
        for (int i = 0; i < 2; i++) {   // B: 16x128 = 512 float4
            int lin = tid + i * 256;
            int kk = lin >> 5, c4 = (lin & 31) * 4;
            float4 v = *reinterpret_cast<const float4*>(
                &g_Ucat[(size_t)(kbase + kk + k0) * N4 + colBase + c4]);
            *reinterpret_cast<float4*>(&Bs[kk][c4]) = v;
        }
        __syncthreads();
        #pragma unroll
        for (int kk = 0; kk < 16; kk++) {
            float4 av = *reinterpret_cast<const float4*>(&As[kk][ty * 4]);
            float4 b0 = *reinterpret_cast<const float4*>(&Bs[kk][tx * 8]);
            float4 b1 = *reinterpret_cast<const float4*>(&Bs[kk][tx * 8 + 4]);
            float a[4] = {av.x, av.y, av.z, av.w};
            float b[8] = {b0.x, b0.y, b0.z, b0.w, b1.x, b1.y, b1.z, b1.w};
            #pragma unroll
            for (int i = 0; i < 4; i++)
                #pragma unroll
                for (int j = 0; j < 8; j++)
                    acc[i][j] += a[i] * b[j];
        }
        __syncthreads();
    }
    float* out = g_preK + (size_t)s * B_ * N4;
    #pragma unroll
    for (int i = 0; i < 4; i++) {
        int r = ty * 4 + i;
        float4 v0 = {acc[i][0], acc[i][1], acc[i][2], acc[i][3]};
        float4 v1 = {acc[i][4], acc[i][5], acc[i][6], acc[i][7]};
        *reinterpret_cast<float4*>(&out[(size_t)r * N4 + colBase + tx * 8])     = v0;
        *reinterpret_cast<float4*>(&out[(size_t)r * N4 + colBase + tx * 8 + 4]) = v1;
    }
}

// ---------------- recurrent step: gates + state update (float4) ----------------
__global__ __launch_bounds__(256) void step_update(int t) {
    int idx = blockIdx.x * blockDim.x + threadIdx.x;   // over B*H/4
    if (idx >= B_ * H_ / 4) return;
    int b = idx / (H_ / 4);
    int j = (idx % (H_ / 4)) * 4;
    const float* Gt = g_G + (size_t)((size_t)t * B_ + b) * N4;
    float4 pf = *reinterpret_cast<const float4*>(&Gt[0 * H_ + j]);
    float4 pi = *reinterpret_cast<const float4*>(&Gt[1 * H_ + j]);
    float4 po = *reinterpret_cast<const float4*>(&Gt[2 * H_ + j]);
    float4 pa = *reinterpret_cast<const float4*>(&Gt[3 * H_ + j]);
    #pragma unroll
    for (int s = 0; s < SPLITK; s++) {
        const float* pk = g_preK + (size_t)s * B_ * N4 + (size_t)b * N4;
        float4 vf = *reinterpret_cast<const float4*>(&pk[0 * H_ + j]);
        float4 vi = *reinterpret_cast<const float4*>(&pk[1 * H_ + j]);
        float4 vo = *reinterpret_cast<const float4*>(&pk[2 * H_ + j]);
        float4 va = *reinterpret_cast<const float4*>(&pk[3 * H_ + j]);
        pf.x += vf.x; pf.y += vf.y; pf.z += vf.z; pf.w += vf.w;
        pi.x += vi.x; pi.y += vi.y; pi.z += vi.z; pi.w += vi.w;
        po.x += vo.x; po.y += vo.y; po.z += vo.z; po.w += vo.w;
        pa.x += va.x; pa.y += va.y; pa.z += va.z; pa.w += va.w;
    }
    float fv[4] = {pf.x, pf.y, pf.z, pf.w};
    float iv[4] = {pi.x, pi.y, pi.z, pi.w};
    float ov[4] = {po.x, po.y, po.z, po.w};
    float av[4] = {pa.x, pa.y, pa.z, pa.w};
    size_t base = (size_t)b * H_ + j;
    float4 cprev = *reinterpret_cast<const float4*>(&g_c[base]);
    float cp[4] = {cprev.x, cprev.y, cprev.z, cprev.w};
    float cnv[4], hnv[4];
    #pragma unroll
    for (int q = 0; q < 4; q++) {
        float ff = 1.f / (1.f + expf(-fv[q]));
        float ii = 1.f / (1.f + expf(-iv[q]));
        float oo = 1.f / (1.f + expf(-ov[q]));
        float cc = ii * tanhf(av[q]) + ff * cp[q];
        cnv[q] = cc;
        hnv[q] = oo * tanhf(cc);
    }
    float4 cn = {cnv[0], cnv[1], cnv[2], cnv[3]};
    float4 hn = {hnv[0], hnv[1], hnv[2], hnv[3]};
    *reinterpret_cast<float4*>(&g_c[base]) = cn;
    *reinterpret_cast<float4*>(&g_h[(size_t)((t + 1) & 1) * (B_ * H_) + base]) = hn;
    *reinterpret_cast<float4*>(&g_Hbuf[(size_t)t * B_ * H_ + base]) = hn;
}

// ---------------- launch ----------------
extern "C" void kernel_launch(void* const* d_in, const int* in_sizes, int n_in,
                              void* d_out, int out_size) {
    const float* x    = (const float*)d_in[0];
    const float* wfxw = (const float*)d_in[1];
    const float* wfxb = (const float*)d_in[2];
    const float* wixw = (const float*)d_in[3];
    const float* wixb = (const float*)d_in[4];
    const float* woxw = (const float*)d_in[5];
    const float* woxb = (const float*)d_in[6];
    const float* wcxw = (const float*)d_in[7];
    const float* wcxb = (const float*)d_in[8];
    const float* ufhw = (const float*)d_in[9];
    const float* uihw = (const float*)d_in[10];
    const float* uohw = (const float*)d_in[11];
    const float* uchw = (const float*)d_in[12];
    const float* fcow = (const float*)d_in[13];
    const float* fcob = (const float*)d_in[14];
    float* out = (float*)d_out;

    init_state<<<(2 * B_ * H_ + 255) / 256, 256>>>();
    build_W<<<(Fdim * N4 + 255) / 256, 256>>>(wfxw, wixw, woxw, wcxw);
    build_bias<<<(N4 + 255) / 256, 256>>>(wfxb, wixb, woxb, wcxb);
    build_U<<<(H_ * N4 + 255) / 256, 256>>>(ufhw, uihw, uohw, uchw);

    {   // input projections: G = x @ Wcat + bias
        dim3 grid(N4 / 128, (T_ * B_) / 128);
        gemm_in<<<grid, 256>>>(x);
    }

    for (int t = 0; t < T_; t++) {
        dim3 grid(N4 / 128, SPLITK);   // 32 x 8 = 256 CTAs
        step_gemm<<<grid, 256>>>(t);
        step_update<<<(B_ * H_ / 4 + 255) / 256, 256>>>(t);
    }

    {   // output projection: out = Hbuf @ fco_w + fco_b
        dim3 grid((FO + 127) / 128, (T_ * B_) / 128);
        gemm_out<<<grid, 256>>>(fcow, fcob, out);
    }
}

// round 7
// speedup vs baseline: 1.2516x; 1.0181x over previous
#include <cuda_runtime.h>
#include <math.h>

// Quaternion LSTM: T=128, B=64, F=512, H=1024.
// Round 7: persistent recurrence kernel — all 128 steps in ONE launch with a
// custom grid barrier (release/acquire via __threadfence = CCTL.IVALL on B300).
// GEMM + update math identical to round 6 (passed, rel_err 6.6e-7).

#define T_ 128
#define B_ 64
#define Fdim 512
#define H_ 1024
#define N4 (4 * H_)          // 4096
#define FO (Fdim + 1)        // 513
#define SPLITK 8
#define KCHUNK (H_ / SPLITK) // 128
#define NCTA 256

// ---- scratch (static device globals: allocation-free) ----
__device__ float g_Wcat[(size_t)Fdim * N4];            //  8 MB
__device__ float g_bias4[N4];
__device__ float g_Ucat[(size_t)H_ * N4];              // 16 MB
__device__ float g_G[(size_t)T_ * B_ * N4];            // 128 MB (pre-gates)
__device__ float g_preK[(size_t)SPLITK * B_ * N4];     //  8 MB
__device__ float g_h[B_ * H_];
__device__ float g_c[B_ * H_];
__device__ float g_Hbuf[(size_t)T_ * B_ * H_];         // 32 MB

// grid barrier state
__device__ unsigned g_cnt;
__device__ volatile unsigned g_gen;

__device__ const float c_sgn[16] = {
    1.f, -1.f, -1.f, -1.f,
    1.f,  1.f, -1.f,  1.f,
    1.f,  1.f,  1.f, -1.f,
    1.f, -1.f,  1.f,  1.f
};

// ---------------- init ----------------
__global__ void init_state() {
    int idx = blockIdx.x * blockDim.x + threadIdx.x;
    if (idx < B_ * H_) { g_h[idx] = 0.f; g_c[idx] = 0.f; }
    if (idx == 0) { g_cnt = 0; g_gen = 0; }
}

// ---------------- build Hamilton matrices ----------------
__global__ void build_W(const float* __restrict__ wf, const float* __restrict__ wi,
                        const float* __restrict__ wo, const float* __restrict__ wc) {
    int idx = blockIdx.x * blockDim.x + threadIdx.x;
    if (idx >= Fdim * N4) return;
    int row  = idx / N4;
    int col  = idx % N4;
    int gate = col / H_;
    int cj   = col % H_;
    int rb = row / (Fdim / 4), a = row % (Fdim / 4);
    int cb = cj / (H_ / 4),    b = cj % (H_ / 4);
    const float* w = (gate == 0) ? wf : (gate == 1) ? wi : (gate == 2) ? wo : wc;
    g_Wcat[idx] = c_sgn[cb * 4 + rb] *
                  w[((size_t)(rb ^ cb) * (Fdim / 4) + a) * (H_ / 4) + b];
}

__global__ void build_U(const float* __restrict__ uf, const float* __restrict__ ui,
                        const float* __restrict__ uo, const float* __restrict__ uc) {
    int idx = blockIdx.x * blockDim.x + threadIdx.x;
    if (idx >= H_ * N4) return;
    int row  = idx / N4;
    int col  = idx % N4;
    int gate = col / H_;
    int cj   = col % H_;
    int rb = row / (H_ / 4), a = row % (H_ / 4);
    int cb = cj / (H_ / 4),  b = cj % (H_ / 4);
    const float* w = (gate == 0) ? uf : (gate == 1) ? ui : (gate == 2) ? uo : uc;
    g_Ucat[idx] = c_sgn[cb * 4 + rb] *
                  w[((size_t)(rb ^ cb) * (H_ / 4) + a) * (H_ / 4) + b];
}

__global__ void build_bias(const float* __restrict__ bf, const float* __restrict__ bi,
                           const float* __restrict__ bo, const float* __restrict__ bc) {
    int idx = blockIdx.x * blockDim.x + threadIdx.x;
    if (idx >= N4) return;
    int gate = idx / H_, j = idx % H_;
    const float* b = (gate == 0) ? bf : (gate == 1) ? bi : (gate == 2) ? bo : bc;
    g_bias4[idx] = b[j];
}

// ---------------- generic fp32 GEMM (128x128 tile, 8x8 microtile) ----------------
__device__ __forceinline__ void gemm_body(const float* __restrict__ A,
                                          const float* __restrict__ Bm,
                                          const float* __restrict__ bias,
                                          float* __restrict__ C,
                                          int M, int N, int K) {
    const int BM = 128, BN = 128, BK = 16;
    __shared__ float As[BK][BM];
    __shared__ float Bs[BK][BN];
    int tid = threadIdx.x;
    int tx = tid % 16, ty = tid / 16;
    int rowBase = blockIdx.y * BM;
    int colBase = blockIdx.x * BN;
    float acc[8][8];
    #pragma unroll
    for (int i = 0; i < 8; i++)
        #pragma unroll
        for (int j = 0; j < 8; j++) acc[i][j] = 0.f;

    for (int k0 = 0; k0 < K; k0 += BK) {
        #pragma unroll
        for (int i = 0; i < 2; i++) {
            int lin = tid + i * 256;
            int r = lin >> 2, c4 = (lin & 3) * 4;
            float4 v = *reinterpret_cast<const float4*>(
                &A[(size_t)(rowBase + r) * K + k0 + c4]);
            As[c4 + 0][r] = v.x;
            As[c4 + 1][r] = v.y;
            As[c4 + 2][r] = v.z;
            As[c4 + 3][r] = v.w;
        }
        #pragma unroll
        for (int i = 0; i < 8; i++) {
            int lin = tid + i * 256;
            int kk = lin >> 7, n = lin & 127;
            int gn = colBase + n;
            float v = 0.f;
            if (gn < N) v = Bm[(size_t)(k0 + kk) * N + gn];
            Bs[kk][n] = v;
        }
        __syncthreads();
        #pragma unroll
        for (int kk = 0; kk < BK; kk++) {
            float a[8], b[8];
            float4 a0 = *reinterpret_cast<const float4*>(&As[kk][ty * 8]);
            float4 a1 = *reinterpret_cast<const float4*>(&As[kk][ty * 8 + 4]);
            float4 b0 = *reinterpret_cast<const float4*>(&Bs[kk][tx * 8]);
            float4 b1 = *reinterpret_cast<const float4*>(&Bs[kk][tx * 8 + 4]);
            a[0]=a0.x; a[1]=a0.y; a[2]=a0.z; a[3]=a0.w;
            a[4]=a1.x; a[5]=a1.y; a[6]=a1.z; a[7]=a1.w;
            b[0]=b0.x; b[1]=b0.y; b[2]=b0.z; b[3]=b0.w;
            b[4]=b1.x; b[5]=b1.y; b[6]=b1.z; b[7]=b1.w;
            #pragma unroll
            for (int i = 0; i < 8; i++)
                #pragma unroll
                for (int j = 0; j < 8; j++)
                    acc[i][j] += a[i] * b[j];
        }
        __syncthreads();
    }
    #pragma unroll
    for (int i = 0; i < 8; i++) {
        int gm = rowBase + ty * 8 + i;
        if (gm >= M) continue;
        #pragma unroll
        for (int j = 0; j < 8; j++) {
            int gn = colBase + tx * 8 + j;
            if (gn >= N) continue;
            float v = acc[i][j];
            if (bias) v += bias[gn];
            C[(size_t)gm * N + gn] = v;
        }
    }
}

__global__ __launch_bounds__(256) void gemm_in(const float* __restrict__ x) {
    gemm_body(x, g_Wcat, g_bias4, g_G, T_ * B_, N4, Fdim);
}

__global__ __launch_bounds__(256) void gemm_out(const float* __restrict__ fw,
                                                const float* __restrict__ fb,
                                                float* __restrict__ out) {
    gemm_body(g_Hbuf, fw, fb, out, T_ * B_, FO, H_);
}

// ---------------- grid barrier (all NCTA CTAs resident) ----------------
__device__ __forceinline__ void grid_barrier() {
    __syncthreads();
    __threadfence();   // release: this CTA's global writes visible device-wide
    if (threadIdx.x == 0) {
        unsigned gen = g_gen;
        unsigned prev = atomicAdd(&g_cnt, 1u);
        if (prev == NCTA - 1) {
            g_cnt = 0;
            __threadfence();
            g_gen = gen + 1;
        } else {
            while (g_gen == gen) { }
        }
    }
    __syncthreads();
    __threadfence();   // acquire: CCTL.IVALL flushes stale L1 before next reads
}

// ---------------- persistent recurrence: all 128 steps in one launch ----------
// 256 CTAs x 256 threads, >=2 CTAs/SM guaranteed -> all co-resident (wave 1).
__global__ __launch_bounds__(256, 2) void recurrence() {
    __shared__ float As[16][68];
    __shared__ float Bs[16][132];
    int tid = threadIdx.x;
    int tx = tid & 15, ty = tid >> 4;
    int nTile = blockIdx.x & 31;
    int s = blockIdx.x >> 5;
    int colBase = nTile * 128;
    int kbase = s * KCHUNK;
    int gtid = blockIdx.x * 256 + tid;
    float* preOut = g_preK + (size_t)s * B_ * N4;

    for (int t = 0; t < T_; t++) {
        // ======== phase 1: pre = h @ Ucat (this CTA: 64 x 128 tile, K chunk s)
        float acc[4][8];
        #pragma unroll
        for (int i = 0; i < 4; i++)
            #pragma unroll
            for (int j = 0; j < 8; j++) acc[i][j] = 0.f;

        for (int k0 = 0; k0 < KCHUNK; k0 += 16) {
            {   // A: 64x16 = 256 float4, one per thread (transposed store)
                int r = tid >> 2, c4 = (tid & 3) * 4;
                float4 v = *reinterpret_cast<const float4*>(
                    &g_h[(size_t)r * H_ + kbase + k0 + c4]);
                As[c4 + 0][r] = v.x;
                As[c4 + 1][r] = v.y;
                As[c4 + 2][r] = v.z;
                As[c4 + 3][r] = v.w;
            }
            #pragma unroll
            for (int i = 0; i < 2; i++) {   // B: 16x128 = 512 float4
                int lin = tid + i * 256;
                int kk = lin >> 5, c4 = (lin & 31) * 4;
                float4 v = *reinterpret_cast<const float4*>(
                    &g_Ucat[(size_t)(kbase + kk + k0) * N4 + colBase + c4]);
                *reinterpret_cast<float4*>(&Bs[kk][c4]) = v;
            }
            __syncthreads();
            #pragma unroll
            for (int kk = 0; kk < 16; kk++) {
                float4 av = *reinterpret_cast<const float4*>(&As[kk][ty * 4]);
                float4 b0 = *reinterpret_cast<const float4*>(&Bs[kk][tx * 8]);
                float4 b1 = *reinterpret_cast<const float4*>(&Bs[kk][tx * 8 + 4]);
                float a[4] = {av.x, av.y, av.z, av.w};
                float b[8] = {b0.x, b0.y, b0.z, b0.w, b1.x, b1.y, b1.z, b1.w};
                #pragma unroll
                for (int i = 0; i < 4; i++)
                    #pragma unroll
                    for (int j = 0; j < 8; j++)
                        acc[i][j] += a[i] * b[j];
            }
            __syncthreads();
        }
        #pragma unroll
        for (int i = 0; i < 4; i++) {
            int r = ty * 4 + i;
            float4 v0 = {acc[i][0], acc[i][1], acc[i][2], acc[i][3]};
            float4 v1 = {acc[i][4], acc[i][5], acc[i][6], acc[i][7]};
            *reinterpret_cast<float4*>(&preOut[(size_t)r * N4 + colBase + tx * 8])     = v0;
            *reinterpret_cast<float4*>(&preOut[(size_t)r * N4 + colBase + tx * 8 + 4]) = v1;
        }

        grid_barrier();

        // ======== phase 2: gates + state update (threads 0..16383 active)
        if (gtid < B_ * H_ / 4) {
            int b = gtid / (H_ / 4);
            int j = (gtid % (H_ / 4)) * 4;
            const float* Gt = g_G + (size_t)((size_t)t * B_ + b) * N4;
            float4 pf = *reinterpret_cast<const float4*>(&Gt[0 * H_ + j]);
            float4 pi = *reinterpret_cast<const float4*>(&Gt[1 * H_ + j]);
            float4 po = *reinterpret_cast<const float4*>(&Gt[2 * H_ + j]);
            float4 pa = *reinterpret_cast<const float4*>(&Gt[3 * H_ + j]);
            #pragma unroll
            for (int sp = 0; sp < SPLITK; sp++) {
                const float* pk = g_preK + (size_t)sp * B_ * N4 + (size_t)b * N4;
                float4 vf = *reinterpret_cast<const float4*>(&pk[0 * H_ + j]);
                float4 vi = *reinterpret_cast<const float4*>(&pk[1 * H_ + j]);
                float4 vo = *reinterpret_cast<const float4*>(&pk[2 * H_ + j]);
                float4 va = *reinterpret_cast<const float4*>(&pk[3 * H_ + j]);
                pf.x += vf.x; pf.y += vf.y; pf.z += vf.z; pf.w += vf.w;
                pi.x += vi.x; pi.y += vi.y; pi.z += vi.z; pi.w += vi.w;
                po.x += vo.x; po.y += vo.y; po.z += vo.z; po.w += vo.w;
                pa.x += va.x; pa.y += va.y; pa.z += va.z; pa.w += va.w;
            }
            float fv[4] = {pf.x, pf.y, pf.z, pf.w};
            float iv[4] = {pi.x, pi.y, pi.z, pi.w};
            float ov[4] = {po.x, po.y, po.z, po.w};
            float av[4] = {pa.x, pa.y, pa.z, pa.w};
            size_t base = (size_t)b * H_ + j;
            float4 cprev = *reinterpret_cast<const float4*>(&g_c[base]);
            float cp[4] = {cprev.x, cprev.y, cprev.z, cprev.w};
            float cnv[4], hnv[4];
            #pragma unroll
            for (int q = 0; q < 4; q++) {
                float ff = 1.f / (1.f + expf(-fv[q]));
                float ii = 1.f / (1.f + expf(-iv[q]));
                float oo = 1.f / (1.f + expf(-ov[q]));
                float cc = ii * tanhf(av[q]) + ff * cp[q];
                cnv[q] = cc;
                hnv[q] = oo * tanhf(cc);
            }
            float4 cn = {cnv[0], cnv[1], cnv[2], cnv[3]};
            float4 hn = {hnv[0], hnv[1], hnv[2], hnv[3]};
            *reinterpret_cast<float4*>(&g_c[base]) = cn;
            *reinterpret_cast<float4*>(&g_h[base]) = hn;
            *reinterpret_cast<float4*>(&g_Hbuf[(size_t)t * B_ * H_ + base]) = hn;
        }

        grid_barrier();
    }
}

// ---------------- launch ----------------
extern "C" void kernel_launch(void* const* d_in, const int* in_sizes, int n_in,
                              void* d_out, int out_size) {
    const float* x    = (const float*)d_in[0];
    const float* wfxw = (const float*)d_in[1];
    const float* wfxb = (const float*)d_in[2];
    const float* wixw = (const float*)d_in[3];
    const float* wixb = (const float*)d_in[4];
    const float* woxw = (const float*)d_in[5];
    const float* woxb = (const float*)d_in[6];
    const float* wcxw = (const float*)d_in[7];
    const float* wcxb = (const float*)d_in[8];
    const float* ufhw = (const float*)d_in[9];
    const float* uihw = (const float*)d_in[10];
    const float* uohw = (const float*)d_in[11];
    const float* uchw = (const float*)d_in[12];
    const float* fcow = (const float*)d_in[13];
    const float* fcob = (const float*)d_in[14];
    float* out = (float*)d_out;

    init_state<<<(B_ * H_ + 255) / 256, 256>>>();
    build_W<<<(Fdim * N4 + 255) / 256, 256>>>(wfxw, wixw, woxw, wcxw);
    build_bias<<<(N4 + 255) / 256, 256>>>(wfxb, wixb, woxb, wcxb);
    build_U<<<(H_ * N4 + 255) / 256, 256>>>(ufhw, uihw, uohw, uchw);

    {   // input projections: G = x @ Wcat + bias
        dim3 grid(N4 / 128, (T_ * B_) / 128);
        gemm_in<<<grid, 256>>>(x);
    }

    // all 128 recurrent steps in a single persistent launch
    recurrence<<<NCTA, 256>>>();

    {   // output projection: out = Hbuf @ fco_w + fco_b
        dim3 grid((FO + 127) / 128, (T_ * B_) / 128);
        gemm_out<<<grid, 256>>>(fcow, fcob, out);
    }
}